// round 14
// baseline (speedup 1.0000x reference)
#include <cuda_runtime.h>

// Row-wise cumulative product, rows of 32768 fp32, one CTA per row.
// 512 threads x 8 contiguous elems (2 x float4) = 4096 elems/tile, 8 tiles.
// Depth-2 prefetch: up to 4 LDG.128 in flight per thread during the scan,
// and 2 CTAs/SM so one CTA's barrier phase overlaps the other's loads.
// Single barrier per tile; every warp redundantly scans the 16 warp totals.

#define COLS     32768
#define THREADS  512
#define EPT      8
#define TILE     (THREADS * EPT)        // 4096
#define TILE4    (TILE / 4)             // 1024 float4s per tile
#define NTILES   (COLS / TILE)          // 8
#define NWARPS   (THREADS / 32)         // 16

__global__ __launch_bounds__(THREADS, 2)
void cumprod_rows_kernel(const float4* __restrict__ in, float4* __restrict__ out)
{
    const int row  = blockIdx.x;
    const int t    = threadIdx.x;
    const int lane = t & 31;
    const int warp = t >> 5;

    const float4* rin  = in  + (size_t)row * (COLS / 4);
    float4*       rout = out + (size_t)row * (COLS / 4);

    __shared__ float warp_prod[2][NWARPS];

    float carry = 1.0f;

    // depth-2 prefetch: tiles 0 and 1
    const int ti = t * 2;
    float4 a0 = __ldcs(&rin[ti]);
    float4 b0 = __ldcs(&rin[ti + 1]);
    float4 a1 = __ldcs(&rin[TILE4 + ti]);
    float4 b1 = __ldcs(&rin[TILE4 + ti + 1]);

    #pragma unroll
    for (int tile = 0; tile < NTILES; ++tile) {
        const int buf = tile & 1;
        float4 ca = a0, cb = b0;
        a0 = a1;  b0 = b1;
        if (tile + 2 < NTILES) {
            a1 = __ldcs(&rin[(tile + 2) * TILE4 + ti]);
            b1 = __ldcs(&rin[(tile + 2) * TILE4 + ti + 1]);
        }

        // thread-local inclusive products over 8 contiguous elems
        float p0 = ca.x;
        float p1 = p0 * ca.y;
        float p2 = p1 * ca.z;
        float p3 = p2 * ca.w;
        float p4 = p3 * cb.x;
        float p5 = p4 * cb.y;
        float p6 = p5 * cb.z;
        float p7 = p6 * cb.w;

        // warp inclusive multiplicative scan of p7
        float incl = p7;
        #pragma unroll
        for (int o = 1; o < 32; o <<= 1) {
            float n = __shfl_up_sync(0xffffffffu, incl, o);
            if (lane >= o) incl *= n;
        }

        // lane-exclusive prefix within warp
        float excl = __shfl_up_sync(0xffffffffu, incl, 1);
        if (lane == 0) excl = 1.0f;

        if (lane == 31) warp_prod[buf][warp] = incl;
        __syncthreads();   // the ONLY barrier this tile

        // every warp scans the 16 warp totals itself (mirrored in both
        // 16-lane halves so the shfl_up stays within each half)
        float w = warp_prod[buf][lane & 15];
        #pragma unroll
        for (int o = 1; o < 16; o <<= 1) {
            float n = __shfl_up_sync(0xffffffffu, w, o);
            if ((lane & 15) >= o) w *= n;
        }
        float wexcl = __shfl_sync(0xffffffffu, w, (warp == 0) ? 0 : (warp - 1));
        if (warp == 0) wexcl = 1.0f;
        const float tot = __shfl_sync(0xffffffffu, w, NWARPS - 1);

        const float prefix = carry * wexcl * excl;

        float4 oa, ob;
        oa.x = prefix * p0;  oa.y = prefix * p1;
        oa.z = prefix * p2;  oa.w = prefix * p3;
        ob.x = prefix * p4;  ob.y = prefix * p5;
        ob.z = prefix * p6;  ob.w = prefix * p7;
        __stcs(&rout[tile * TILE4 + ti],     oa);
        __stcs(&rout[tile * TILE4 + ti + 1], ob);

        carry *= tot;
        // no trailing barrier: next tile uses the other warp_prod buffer
    }
}

extern "C" void kernel_launch(void* const* d_in, const int* in_sizes, int n_in,
                              void* d_out, int out_size)
{
    const float* x = (const float*)d_in[0];
    float*       y = (float*)d_out;
    const int total = in_sizes[0];
    const int rows  = total / COLS;

    cumprod_rows_kernel<<<rows, THREADS>>>((const float4*)x, (float4*)y);
}

// round 16
// speedup vs baseline: 1.0002x; 1.0002x over previous
#include <cuda_runtime.h>

// Row-wise cumulative product, rows of 32768 fp32.
// R3 shape (1024 threads, float4/thread/tile, single barrier, redundant
// warp-total scan, ldcs/stcs) + 2 rows per CTA with prefetch carried
// seamlessly across the row boundary to amortize the cold-start ramp.

#define COLS     32768
#define THREADS  1024
#define ROWS_PER_CTA 2
#define TILE4    THREADS                       // 1024 float4 = 4096 elems/tile
#define NTILES   (COLS / (TILE4 * 4))          // 8 tiles per row
#define TOTTILES (NTILES * ROWS_PER_CTA)       // 16 flat tiles per CTA
#define ROW4     (COLS / 4)                    // 8192 float4 per row

__global__ __launch_bounds__(THREADS, 2)
void cumprod_rows_kernel(const float4* __restrict__ in, float4* __restrict__ out)
{
    const int t    = threadIdx.x;
    const int lane = t & 31;
    const int warp = t >> 5;

    const size_t base = (size_t)blockIdx.x * ROWS_PER_CTA * ROW4;
    const float4* rin  = in  + base;
    float4*       rout = out + base;

    __shared__ float warp_prod[2][32];

    float carry = 1.0f;

    // flat-tile offset helper: tile ft (0..15) -> float4 index
    // (ft >> 3) selects the row, (ft & 7) the tile within the row
    #define FT_OFF(ft) (((ft) >> 3) * ROW4 + ((ft) & 7) * TILE4 + t)

    // prefetch flat tile 0
    float4 v = __ldcs(&rin[FT_OFF(0)]);

    #pragma unroll
    for (int ft = 0; ft < TOTTILES; ++ft) {
        const int buf = ft & 1;
        float4 cur = v;
        // prefetch next flat tile (crosses the row boundary seamlessly)
        if (ft + 1 < TOTTILES)
            v = __ldcs(&rin[FT_OFF(ft + 1)]);

        // thread-local inclusive products
        float p0 = cur.x;
        float p1 = p0 * cur.y;
        float p2 = p1 * cur.z;
        float p3 = p2 * cur.w;

        // warp inclusive multiplicative scan of p3
        float incl = p3;
        #pragma unroll
        for (int o = 1; o < 32; o <<= 1) {
            float n = __shfl_up_sync(0xffffffffu, incl, o);
            if (lane >= o) incl *= n;
        }

        // lane-exclusive prefix within warp
        float excl = __shfl_up_sync(0xffffffffu, incl, 1);
        if (lane == 0) excl = 1.0f;

        if (lane == 31) warp_prod[buf][warp] = incl;
        __syncthreads();   // the ONLY barrier this tile

        // every warp redundantly scans the 32 warp totals
        float w = warp_prod[buf][lane];
        #pragma unroll
        for (int o = 1; o < 32; o <<= 1) {
            float n = __shfl_up_sync(0xffffffffu, w, o);
            if (lane >= o) w *= n;
        }
        float wexcl = __shfl_sync(0xffffffffu, w, (warp == 0) ? 0 : (warp - 1));
        if (warp == 0) wexcl = 1.0f;
        const float tot = __shfl_sync(0xffffffffu, w, 31);

        const float prefix = carry * wexcl * excl;

        float4 o4;
        o4.x = prefix * p0;
        o4.y = prefix * p1;
        o4.z = prefix * p2;
        o4.w = prefix * p3;
        __stcs(&rout[FT_OFF(ft)], o4);

        // advance carry; reset at row boundaries
        carry = ((ft & 7) == 7) ? 1.0f : carry * tot;
        // no trailing barrier: next tile uses the other warp_prod buffer
    }
    #undef FT_OFF
}

extern "C" void kernel_launch(void* const* d_in, const int* in_sizes, int n_in,
                              void* d_out, int out_size)
{
    const float* x = (const float*)d_in[0];
    float*       y = (float*)d_out;
    const int total = in_sizes[0];
    const int rows  = total / COLS;

    cumprod_rows_kernel<<<rows / ROWS_PER_CTA, THREADS>>>((const float4*)x, (float4*)y);
}